// round 7
// baseline (speedup 1.0000x reference)
#include <cuda_runtime.h>
#include <cstdint>

#define BB 4
#define NPTS 20000
#define CC 512
#define MM 1024
#define GRASP_TH 0.1f

#define FPS_THREADS 512
#define FPS_WARPS (FPS_THREADS / 32)   // 16
#define CAPR 10                        // register-resident points per thread
#define PAIRS (CAPR / 2)
#define REGN (FPS_THREADS * CAPR)      // 5120 register-resident points
#define CELLS 512                      // 8x8x8 Morton cells

// ---------------- scratch (static device allocations; no cudaMalloc) -------
__device__ float4 g_cp[BB * NPTS];    // compacted xyz (compaction order)
__device__ int    g_cidx[BB * NPTS];  // compacted -> original index
__device__ int    g_cell[BB * NPTS];  // Morton cell per compacted point
__device__ float4 g_scp[BB * NPTS];   // Morton-sorted points, .w = oidx bits
__device__ float  g_mind[BB * NPTS];  // FPS min-dist (gmem fallback region only)
__device__ int    g_fps[BB * MM];     // sampled ORIGINAL indices
__device__ int    g_nn[BB * MM * 3];  // 3-NN indices
__device__ float  g_w[BB * MM * 3];   // normalized IDW weights
__device__ float4 g_pc4[BB * NPTS];   // full cloud packed as float4

__device__ __forceinline__ float finf()  { return __int_as_float(0x7f800000); }

// packed f32x2 helpers (per-component IEEE rn => bit-exact vs scalar)
#define ADD2(out, a, b) asm("add.rn.f32x2 %0, %1, %2;" : "=l"(out) : "l"(a), "l"(b))
#define MUL2(out, a, b) asm("mul.rn.f32x2 %0, %1, %2;" : "=l"(out) : "l"(a), "l"(b))
#define PACK2(out, lo, hi) asm("mov.b64 %0, {%1, %2};" : "=l"(out) : "r"(lo), "r"(hi))
#define UNPACK2(lo, hi, in) asm("mov.b64 {%0, %1}, %2;" : "=r"(lo), "=r"(hi) : "l"(in))

__device__ __forceinline__ int part3(int v) {
    return (v & 1) | ((v & 2) << 1) | ((v & 4) << 2);
}
__device__ __forceinline__ int cell_of(float x, float y, float z) {
    int cx = min(7, max(0, (int)(x * 8.0f)));
    int cy = min(7, max(0, (int)(y * 8.0f)));
    int cz = min(7, max(0, (int)(z * 8.0f)));
    return part3(cx) | (part3(cy) << 1) | (part3(cz) << 2);
}

// ============================================================================
// Kernel 0: pack full cloud into float4 for LDS.128 in nn_kernel
// ============================================================================
__global__ __launch_bounds__(256)
void pack_kernel(const float* __restrict__ pc)
{
    int e = blockIdx.x * 256 + threadIdx.x;
    if (e < BB * NPTS) {
        const float* p = pc + (size_t)e * 3;
        g_pc4[e] = make_float4(p[0], p[1], p[2], 0.0f);
    }
}

// ============================================================================
// Kernel 1: masked FPS with Morton sort + conservative box pruning.
// One block per batch. Picks are bit-identical to brute force: skips happen
// only when the box lower bound (with 1e-5 margin >> fp rounding) proves no
// owned mind can change; all tie-breaks use ORIGINAL index.
// ============================================================================
__global__ __launch_bounds__(FPS_THREADS, 1)
void fps_kernel(const float* __restrict__ pc,
                const float* __restrict__ obj,
                const float* __restrict__ gr)
{
    const int b    = blockIdx.x;
    const int tid  = threadIdx.x;
    const int lane = tid & 31;
    const int wid  = tid >> 5;

    __shared__ int s_wsum[FPS_WARPS];
    __shared__ int s_base;
    __shared__ int s_cnt[CELLS];
    __shared__ int s_ws[FPS_WARPS];
    __shared__ int s_off[CELLS];
    __shared__ unsigned long long s_val[2][FPS_WARPS];  // (valBits<<32)|~oidx
    __shared__ int                s_pos[2][FPS_WARPS];  // sorted position

    if (tid == 0) s_base = 0;
    __syncthreads();

    const float* objb = obj + (size_t)b * 2 * NPTS;
    const float* grb  = gr  + (size_t)b * NPTS;
    const float* pcb  = pc  + (size_t)b * NPTS * 3;

    // ---- order-preserving compaction of masked points ----
    for (int start = 0; start < NPTS; start += FPS_THREADS) {
        int i = start + tid;
        bool p = false;
        if (i < NPTS)
            p = (objb[NPTS + i] > objb[i]) && (grb[i] > GRASP_TH);
        unsigned bal = __ballot_sync(0xffffffffu, p);
        int wcnt = __popc(bal);
        int wpre = __popc(bal & ((1u << lane) - 1u));
        if (lane == 0) s_wsum[wid] = wcnt;
        __syncthreads();
        if (tid == 0) {
            int acc = s_base;
            #pragma unroll
            for (int w = 0; w < FPS_WARPS; ++w) { int c = s_wsum[w]; s_wsum[w] = acc; acc += c; }
            s_base = acc;
        }
        __syncthreads();
        if (p) {
            int pos = s_wsum[wid] + wpre;
            g_cidx[b * NPTS + pos] = i;
            float4 q;
            q.x = pcb[3 * i]; q.y = pcb[3 * i + 1]; q.z = pcb[3 * i + 2]; q.w = 0.0f;
            g_cp[b * NPTS + pos] = q;
        }
        __syncthreads();
    }
    const int cnt = s_base;

    if (cnt == 0) {
        for (int j = tid; j < MM; j += FPS_THREADS) g_fps[b * MM + j] = 0;
        return;
    }

    const float4* cp = g_cp + b * NPTS;

    // ---- Morton counting sort ----
    if (tid < CELLS) s_cnt[tid] = 0;
    __syncthreads();
    for (int i = tid; i < cnt; i += FPS_THREADS) {
        float4 q = cp[i];
        int mc = cell_of(q.x, q.y, q.z);
        g_cell[b * NPTS + i] = mc;
        atomicAdd(&s_cnt[mc], 1);
    }
    __syncthreads();
    // block exclusive scan over 512 cell counts
    {
        int v = s_cnt[tid];
        int x = v;
        #pragma unroll
        for (int o = 1; o < 32; o <<= 1) {
            int t = __shfl_up_sync(0xffffffffu, x, o);
            if (lane >= o) x += t;
        }
        if (lane == 31) s_ws[wid] = x;
        __syncthreads();
        if (tid < 32) {
            int y = (tid < FPS_WARPS) ? s_ws[tid] : 0;
            #pragma unroll
            for (int o = 1; o < 16; o <<= 1) {
                int t = __shfl_up_sync(0xffffffffu, y, o);
                if (tid >= o) y += t;
            }
            if (tid < FPS_WARPS) s_ws[tid] = y;    // inclusive warp sums
        }
        __syncthreads();
        int base = wid ? s_ws[wid - 1] : 0;
        s_off[tid] = base + x - v;                  // exclusive prefix
    }
    __syncthreads();
    // scatter (order within cell nondeterministic; picks keyed on value+oidx)
    for (int i = tid; i < cnt; i += FPS_THREADS) {
        int mc = g_cell[b * NPTS + i];
        int p = atomicAdd(&s_off[mc], 1);
        float4 q = cp[i];
        q.w = __int_as_float(g_cidx[b * NPTS + i]);
        g_scp[b * NPTS + p] = q;
    }
    __syncthreads();

    const float4* scp = g_scp + b * NPTS;
    const int regCnt = min(cnt, REGN);
    const bool havefb = (cnt > REGN);
    const int firstOidx = g_cidx[b * NPTS];

    // ---- load owned (contiguous sorted) points; build box ----
    const int base = tid * CAPR;
    unsigned long long rx2[PAIRS], ry2[PAIRS], rz2[PAIRS];
    float md[CAPR];
    unsigned ox[CAPR];
    float bxlo = finf(), bylo = finf(), bzlo = finf();
    float bxhi = -finf(), byhi = -finf(), bzhi = -finf();
    #pragma unroll
    for (int p = 0; p < PAIRS; ++p) {
        float c[2][3];
        #pragma unroll
        for (int h = 0; h < 2; ++h) {
            const int k = 2 * p + h;
            int i = base + k;
            if (i < regCnt) {
                float4 q = scp[i];
                c[h][0] = q.x; c[h][1] = q.y; c[h][2] = q.z;
                ox[k] = __float_as_uint(q.w);   // oidx bits (< 2^31, exact)
                md[k] = finf();
                bxlo = fminf(bxlo, q.x); bxhi = fmaxf(bxhi, q.x);
                bylo = fminf(bylo, q.y); byhi = fmaxf(byhi, q.y);
                bzlo = fminf(bzlo, q.z); bzhi = fmaxf(bzhi, q.z);
            } else {
                c[h][0] = 0.f; c[h][1] = 0.f; c[h][2] = 0.f;
                ox[k] = 0xffffffffu;
                md[k] = -0.0f;                  // never beats bV under (>, oidx<)
            }
        }
        PACK2(rx2[p], __float_as_uint(c[0][0]), __float_as_uint(c[1][0]));
        PACK2(ry2[p], __float_as_uint(c[0][1]), __float_as_uint(c[1][1]));
        PACK2(rz2[p], __float_as_uint(c[0][2]), __float_as_uint(c[1][2]));
    }
    const int myn = max(0, min(CAPR, regCnt - base));

    // cached thread best (valid whenever owned minds unchanged)
    float    cV = (myn > 0) ? finf() : 0.0f;   // inf forces first-iter update
    unsigned cO = 0xffffffffu;
    int      cP = 0;

    // fallback region init
    float* gmind = g_mind + b * NPTS;
    for (int i = REGN + tid; i < cnt; i += FPS_THREADS) gmind[i] = finf();
    __syncthreads();

    // ---- first pick = first masked point (compaction order) ----
    float4 p0 = cp[0];
    float lx = p0.x, ly = p0.y, lz = p0.z;
    if (tid == 0) g_fps[b * MM] = firstOidx;

    for (int it = 1; it < MM; ++it) {
        const unsigned ph = (unsigned)(it - 1) & 1u;

        float    bV;
        unsigned bO;
        int      bP;

        // --- conservative box lower bound vs cached max ---
        float cdx = fmaxf(fmaxf(bxlo - lx, lx - bxhi), 0.0f);
        float cdy = fmaxf(fmaxf(bylo - ly, ly - byhi), 0.0f);
        float cdz = fmaxf(fmaxf(bzlo - lz, lz - bzhi), 0.0f);
        float lb = cdx * cdx + cdy * cdy + cdz * cdz;
        bool skip = (!havefb) && (lb * 0.99999f >= cV);

        if (skip) {
            bV = cV; bO = cO; bP = cP;
        } else {
            unsigned long long nlx2, nly2, nlz2;
            {
                unsigned nx = __float_as_uint(-lx);
                unsigned ny = __float_as_uint(-ly);
                unsigned nz = __float_as_uint(-lz);
                PACK2(nlx2, nx, nx);
                PACK2(nly2, ny, ny);
                PACK2(nlz2, nz, nz);
            }
            bV = 0.0f; bO = 0xffffffffu; bP = 0;
            #pragma unroll
            for (int p = 0; p < PAIRS; ++p) {
                unsigned long long dx2, dy2, dz2, s2;
                ADD2(dx2, rx2[p], nlx2);
                MUL2(dx2, dx2, dx2);
                ADD2(dy2, ry2[p], nly2);
                MUL2(dy2, dy2, dy2);
                ADD2(s2, dx2, dy2);
                ADD2(dz2, rz2[p], nlz2);
                MUL2(dz2, dz2, dz2);
                ADD2(s2, s2, dz2);           // ((dx2+dy2)+dz2) — XLA order
                unsigned dlo, dhi;
                UNPACK2(dlo, dhi, s2);
                const int k0 = 2 * p, k1 = 2 * p + 1;
                float m0 = fminf(md[k0], __uint_as_float(dlo));
                float m1 = fminf(md[k1], __uint_as_float(dhi));
                md[k0] = m0;
                md[k1] = m1;
                if (m0 > bV || (m0 == bV && ox[k0] < bO)) { bV = m0; bO = ox[k0]; bP = base + k0; }
                if (m1 > bV || (m1 == bV && ox[k1] < bO)) { bV = m1; bO = ox[k1]; bP = base + k1; }
            }
            cV = bV; cO = bO; cP = bP;
        }
        // fallback region (cnt > 5120; pruning disabled in this mode)
        if (havefb) {
            for (int i = REGN + tid; i < cnt; i += FPS_THREADS) {
                float4 q = scp[i];
                float dx = q.x - lx;
                float dy = q.y - ly;
                float dz = q.z - lz;
                float d = __fadd_rn(__fadd_rn(__fmul_rn(dx, dx),
                                              __fmul_rn(dy, dy)),
                                    __fmul_rn(dz, dz));
                float m = fminf(gmind[i], d);
                gmind[i] = m;
                unsigned o = __float_as_uint(q.w);
                if (m > bV || (m == bV && o < bO)) { bV = m; bO = o; bP = i; }
            }
        }

        // --- warp argmax: max value, then min oidx among ties ---
        unsigned vb = __float_as_uint(bV);
        unsigned wv = __reduce_max_sync(0xffffffffu, vb);
        unsigned wo = __reduce_min_sync(0xffffffffu, (vb == wv) ? bO : 0xffffffffu);
        if (vb == wv && bO == wo) {            // unique winner (oidx unique)
            s_val[ph][wid] = ((unsigned long long)wv << 32) | (unsigned)(~wo);
            s_pos[ph][wid] = bP;
        }
        __syncthreads();

        // --- cross-warp argmax over 16 entries, redundant in every warp ---
        unsigned long long e = s_val[ph][lane & (FPS_WARPS - 1)];
        unsigned hv = (unsigned)(e >> 32);
        unsigned lv = (unsigned)e;             // ~oidx
        unsigned gv = __reduce_max_sync(0xffffffffu, hv);
        unsigned gl = __reduce_max_sync(0xffffffffu, (hv == gv) ? lv : 0u);
        unsigned wb2 = __ballot_sync(0xffffffffu, (hv == gv) & (lv == gl));
        int entry = __ffs(wb2) - 1;            // lanes 0..15 hold entries 0..15
        unsigned gOidx = ~gl;

        if (gv == 0u) {                        // degenerate: all minds zero
            gOidx = (unsigned)firstOidx;
            lx = pcb[3 * gOidx];
            ly = pcb[3 * gOidx + 1];
            lz = pcb[3 * gOidx + 2];
        } else {
            int pos = s_pos[ph][entry];
            float4 w = scp[pos];
            lx = w.x; ly = w.y; lz = w.z;
        }

        if (tid == 0) g_fps[b * MM + it] = (int)gOidx;
    }
}

// ============================================================================
// Kernel 2: three_nn — warp serves 4 queries; lane loads each tile point once.
// ============================================================================
#define NNQ 4
#define NNT 256
#define NNW (NNT / 32)
#define QPB (NNW * NNQ)    // 32 queries per block
#define NTS 2048

__global__ __launch_bounds__(NNT, 1)
void nn_kernel()
{
    __shared__ float4 s_pts[NTS];

    const int tid  = threadIdx.x;
    const int lane = tid & 31;
    const int wid  = tid >> 5;
    const int b    = blockIdx.x / (MM / QPB);
    const int q0   = blockIdx.x * QPB + wid * NNQ;

    const float4* pc4b = g_pc4 + (size_t)b * NPTS;

    float qx[NNQ], qy[NNQ], qz[NNQ];
    #pragma unroll
    for (int t = 0; t < NNQ; ++t) {
        const float4 qp = pc4b[g_fps[q0 + t]];
        qx[t] = qp.x; qy[t] = qp.y; qz[t] = qp.z;
    }

    float d0[NNQ], d1[NNQ], d2[NNQ];
    int   i0[NNQ], i1[NNQ], i2[NNQ];
    #pragma unroll
    for (int t = 0; t < NNQ; ++t) {
        d0[t] = finf(); d1[t] = finf(); d2[t] = finf();
        i0[t] = -1;     i1[t] = -1;     i2[t] = -1;
    }

    for (int t0 = 0; t0 < NPTS; t0 += NTS) {
        const int ts = min(NTS, NPTS - t0);
        __syncthreads();
        for (int j = tid; j < ts; j += NNT)
            s_pts[j] = pc4b[t0 + j];
        __syncthreads();

        for (int j = lane; j < ts; j += 32) {
            const float4 w = s_pts[j];
            const int gi = t0 + j;
            #pragma unroll
            for (int t = 0; t < NNQ; ++t) {
                float dx = w.x - qx[t];
                float dy = w.y - qy[t];
                float dz = w.z - qz[t];
                float d = fmaf(dz, dz, fmaf(dy, dy, dx * dx));
                if (d < d2[t]) {
                    if (d < d1[t]) {
                        if (d < d0[t]) { d2[t] = d1[t]; i2[t] = i1[t];
                                         d1[t] = d0[t]; i1[t] = i0[t];
                                         d0[t] = d;     i0[t] = gi; }
                        else           { d2[t] = d1[t]; i2[t] = i1[t];
                                         d1[t] = d;     i1[t] = gi; }
                    } else             { d2[t] = d;     i2[t] = gi; }
                }
            }
        }
    }

    #pragma unroll
    for (int t = 0; t < NNQ; ++t) {
        #pragma unroll
        for (int off = 16; off; off >>= 1) {
            float od0 = __shfl_down_sync(0xffffffffu, d0[t], off);
            float od1 = __shfl_down_sync(0xffffffffu, d1[t], off);
            float od2 = __shfl_down_sync(0xffffffffu, d2[t], off);
            int   oi0 = __shfl_down_sync(0xffffffffu, i0[t], off);
            int   oi1 = __shfl_down_sync(0xffffffffu, i1[t], off);
            int   oi2 = __shfl_down_sync(0xffffffffu, i2[t], off);
            #pragma unroll
            for (int k = 0; k < 3; ++k) {
                float d = (k == 0) ? od0 : (k == 1) ? od1 : od2;
                int   i = (k == 0) ? oi0 : (k == 1) ? oi1 : oi2;
                bool l2 = (d < d2[t]) || (d == d2[t] && i < i2[t]);
                if (l2) {
                    bool l1 = (d < d1[t]) || (d == d1[t] && i < i1[t]);
                    if (l1) {
                        bool l0 = (d < d0[t]) || (d == d0[t] && i < i0[t]);
                        if (l0) { d2[t] = d1[t]; i2[t] = i1[t];
                                  d1[t] = d0[t]; i1[t] = i0[t];
                                  d0[t] = d;     i0[t] = i; }
                        else    { d2[t] = d1[t]; i2[t] = i1[t];
                                  d1[t] = d;     i1[t] = i; }
                    } else      { d2[t] = d;     i2[t] = i; }
                }
            }
        }
        if (lane == 0) {
            const int q = q0 + t;
            float e0 = sqrtf(fmaxf(d0[t], 0.0f));
            float e1 = sqrtf(fmaxf(d1[t], 0.0f));
            float e2 = sqrtf(fmaxf(d2[t], 0.0f));
            float w0 = 1.0f / (e0 + 1e-8f);
            float w1 = 1.0f / (e1 + 1e-8f);
            float w2 = 1.0f / (e2 + 1e-8f);
            float s  = __fadd_rn(__fadd_rn(w0, w1), w2);
            g_w[3 * q + 0] = w0 / s;
            g_w[3 * q + 1] = w1 / s;
            g_w[3 * q + 2] = w2 / s;
            g_nn[3 * q + 0] = i0[t];
            g_nn[3 * q + 1] = i1[t];
            g_nn[3 * q + 2] = i2[t];
        }
    }
}

// ============================================================================
// Kernel 3: IDW feature interpolation.
// ============================================================================
__global__ __launch_bounds__(256)
void interp_kernel(const float* __restrict__ feat, float* __restrict__ out)
{
    int e = blockIdx.x * blockDim.x + threadIdx.x;
    if (e >= BB * CC * MM) return;
    const int m = e % MM;
    const int c = (e / MM) % CC;
    const int b = e / (MM * CC);
    const int q = b * MM + m;

    const int   j0 = g_nn[3 * q],     j1 = g_nn[3 * q + 1], j2 = g_nn[3 * q + 2];
    const float w0 = g_w[3 * q],      w1 = g_w[3 * q + 1],  w2 = g_w[3 * q + 2];
    const float* f = feat + ((size_t)b * CC + c) * NPTS;
    out[e] = w0 * f[j0] + w1 * f[j1] + w2 * f[j2];
}

// ============================================================================
extern "C" void kernel_launch(void* const* d_in, const int* in_sizes, int n_in,
                              void* d_out, int out_size)
{
    const float* pc   = (const float*)d_in[0];  // (B,N,3)
    const float* feat = (const float*)d_in[1];  // (B,C,N)
    const float* obj  = (const float*)d_in[2];  // (B,2,N)
    const float* gr   = (const float*)d_in[3];  // (B,N)
    float* out = (float*)d_out;                 // (B,C,M)

    pack_kernel<<<(BB * NPTS + 255) / 256, 256>>>(pc);
    fps_kernel<<<BB, FPS_THREADS>>>(pc, obj, gr);
    nn_kernel<<<(BB * MM) / QPB, NNT>>>();
    interp_kernel<<<(BB * CC * MM + 255) / 256, 256>>>(feat, out);
}

// round 8
// speedup vs baseline: 1.0441x; 1.0441x over previous
#include <cuda_runtime.h>
#include <cstdint>

#define BB 4
#define NPTS 20000
#define CC 512
#define MM 1024
#define GRASP_TH 0.1f

#define FPS_THREADS 512
#define FPS_WARPS (FPS_THREADS / 32)   // 16
#define CAPR 10                        // register-resident points per thread
#define PAIRS (CAPR / 2)
#define REGN (FPS_THREADS * CAPR)      // 5120 register-resident points
#define CELLS 512                      // 8x8x8 Morton cells

// ---------------- scratch (static device allocations; no cudaMalloc) -------
__device__ float4 g_cp[BB * NPTS];    // compacted xyz (compaction order)
__device__ int    g_cidx[BB * NPTS];  // compacted -> original index
__device__ int    g_cell[BB * NPTS];  // Morton cell per compacted point
__device__ float4 g_scp[BB * NPTS];   // Morton-sorted points, .w = oidx bits
__device__ float  g_mind[BB * NPTS];  // FPS min-dist (gmem fallback region only)
__device__ int    g_fps[BB * MM];     // sampled ORIGINAL indices
__device__ int    g_nn[BB * MM * 3];  // 3-NN indices
__device__ float  g_w[BB * MM * 3];   // normalized IDW weights
__device__ float4 g_pc4[BB * NPTS];   // full cloud packed as float4

__device__ __forceinline__ float finf()  { return __int_as_float(0x7f800000); }

// packed f32x2 helpers (per-component IEEE rn => bit-exact vs scalar)
#define ADD2(out, a, b) asm("add.rn.f32x2 %0, %1, %2;" : "=l"(out) : "l"(a), "l"(b))
#define MUL2(out, a, b) asm("mul.rn.f32x2 %0, %1, %2;" : "=l"(out) : "l"(a), "l"(b))
#define PACK2(out, lo, hi) asm("mov.b64 %0, {%1, %2};" : "=l"(out) : "r"(lo), "r"(hi))
#define UNPACK2(lo, hi, in) asm("mov.b64 {%0, %1}, %2;" : "=r"(lo), "=r"(hi) : "l"(in))

__device__ __forceinline__ int part3(int v) {
    return (v & 1) | ((v & 2) << 1) | ((v & 4) << 2);
}
__device__ __forceinline__ int cell_of(float x, float y, float z) {
    int cx = min(7, max(0, (int)(x * 8.0f)));
    int cy = min(7, max(0, (int)(y * 8.0f)));
    int cz = min(7, max(0, (int)(z * 8.0f)));
    return part3(cx) | (part3(cy) << 1) | (part3(cz) << 2);
}

// ============================================================================
// Kernel 0: pack full cloud into float4 for LDS.128 in nn_kernel
// ============================================================================
__global__ __launch_bounds__(256)
void pack_kernel(const float* __restrict__ pc)
{
    int e = blockIdx.x * 256 + threadIdx.x;
    if (e < BB * NPTS) {
        const float* p = pc + (size_t)e * 3;
        g_pc4[e] = make_float4(p[0], p[1], p[2], 0.0f);
    }
}

// ============================================================================
// Kernel 1: masked FPS, Morton-sorted, WARP-UNIFORM box pruning.
// One block per batch. A warp skips its whole update (and warp reduction)
// when the warp bounding-box lower bound proves no owned mind can change;
// the branch is warp-uniform so skipped work is actually saved.
// Picks are bit-identical: distances use the exact XLA rounding chain, all
// tie-breaks use ORIGINAL index, skip margin 1e-5 >> fp rounding.
// ============================================================================
__global__ __launch_bounds__(FPS_THREADS, 1)
void fps_kernel(const float* __restrict__ pc,
                const float* __restrict__ obj,
                const float* __restrict__ gr)
{
    const int b    = blockIdx.x;
    const int tid  = threadIdx.x;
    const int lane = tid & 31;
    const int wid  = tid >> 5;

    __shared__ int s_wsum[FPS_WARPS];
    __shared__ int s_base;
    __shared__ int s_cnt[CELLS];
    __shared__ int s_ws[FPS_WARPS];
    __shared__ int s_off[CELLS];
    __shared__ unsigned long long s_val[2][FPS_WARPS];  // (valBits<<32)|~oidx
    __shared__ int                s_pos[2][FPS_WARPS];  // sorted position

    if (tid == 0) s_base = 0;
    __syncthreads();

    const float* objb = obj + (size_t)b * 2 * NPTS;
    const float* grb  = gr  + (size_t)b * NPTS;
    const float* pcb  = pc  + (size_t)b * NPTS * 3;

    // ---- order-preserving compaction of masked points ----
    for (int start = 0; start < NPTS; start += FPS_THREADS) {
        int i = start + tid;
        bool p = false;
        if (i < NPTS)
            p = (objb[NPTS + i] > objb[i]) && (grb[i] > GRASP_TH);
        unsigned bal = __ballot_sync(0xffffffffu, p);
        int wcnt = __popc(bal);
        int wpre = __popc(bal & ((1u << lane) - 1u));
        if (lane == 0) s_wsum[wid] = wcnt;
        __syncthreads();
        if (tid == 0) {
            int acc = s_base;
            #pragma unroll
            for (int w = 0; w < FPS_WARPS; ++w) { int c = s_wsum[w]; s_wsum[w] = acc; acc += c; }
            s_base = acc;
        }
        __syncthreads();
        if (p) {
            int pos = s_wsum[wid] + wpre;
            g_cidx[b * NPTS + pos] = i;
            float4 q;
            q.x = pcb[3 * i]; q.y = pcb[3 * i + 1]; q.z = pcb[3 * i + 2]; q.w = 0.0f;
            g_cp[b * NPTS + pos] = q;
        }
        __syncthreads();
    }
    const int cnt = s_base;

    if (cnt == 0) {
        for (int j = tid; j < MM; j += FPS_THREADS) g_fps[b * MM + j] = 0;
        return;
    }

    const float4* cp = g_cp + b * NPTS;

    // ---- Morton counting sort ----
    if (tid < CELLS) s_cnt[tid] = 0;
    __syncthreads();
    for (int i = tid; i < cnt; i += FPS_THREADS) {
        float4 q = cp[i];
        int mc = cell_of(q.x, q.y, q.z);
        g_cell[b * NPTS + i] = mc;
        atomicAdd(&s_cnt[mc], 1);
    }
    __syncthreads();
    // block exclusive scan over 512 cell counts
    {
        int v = s_cnt[tid];
        int x = v;
        #pragma unroll
        for (int o = 1; o < 32; o <<= 1) {
            int t = __shfl_up_sync(0xffffffffu, x, o);
            if (lane >= o) x += t;
        }
        if (lane == 31) s_ws[wid] = x;
        __syncthreads();
        if (tid < 32) {
            int y = (tid < FPS_WARPS) ? s_ws[tid] : 0;
            #pragma unroll
            for (int o = 1; o < 16; o <<= 1) {
                int t = __shfl_up_sync(0xffffffffu, y, o);
                if (tid >= o) y += t;
            }
            if (tid < FPS_WARPS) s_ws[tid] = y;
        }
        __syncthreads();
        int base = wid ? s_ws[wid - 1] : 0;
        s_off[tid] = base + x - v;
    }
    __syncthreads();
    // scatter (order within cell nondeterministic; picks keyed on value+oidx)
    for (int i = tid; i < cnt; i += FPS_THREADS) {
        int mc = g_cell[b * NPTS + i];
        int p = atomicAdd(&s_off[mc], 1);
        float4 q = cp[i];
        q.w = __int_as_float(g_cidx[b * NPTS + i]);
        g_scp[b * NPTS + p] = q;
    }
    __syncthreads();

    const float4* scp = g_scp + b * NPTS;
    const int regCnt = min(cnt, REGN);
    const bool havefb = (cnt > REGN);
    const int firstOidx = g_cidx[b * NPTS];

    // ---- load owned (contiguous sorted) points ----
    const int base = tid * CAPR;
    unsigned long long rx2[PAIRS], ry2[PAIRS], rz2[PAIRS];
    float md[CAPR];
    unsigned ox[CAPR];
    float txlo = finf(), tylo = finf(), tzlo = finf();   // thread box
    float txhi = 0.0f,   tyhi = 0.0f,   tzhi = 0.0f;     // coords >= 0
    #pragma unroll
    for (int p = 0; p < PAIRS; ++p) {
        float c[2][3];
        #pragma unroll
        for (int h = 0; h < 2; ++h) {
            const int k = 2 * p + h;
            int i = base + k;
            if (i < regCnt) {
                float4 q = scp[i];
                c[h][0] = q.x; c[h][1] = q.y; c[h][2] = q.z;
                ox[k] = __float_as_uint(q.w);
                md[k] = finf();
                txlo = fminf(txlo, q.x); txhi = fmaxf(txhi, q.x);
                tylo = fminf(tylo, q.y); tyhi = fmaxf(tyhi, q.y);
                tzlo = fminf(tzlo, q.z); tzhi = fmaxf(tzhi, q.z);
            } else {
                c[h][0] = 0.f; c[h][1] = 0.f; c[h][2] = 0.f;
                ox[k] = 0xffffffffu;
                md[k] = -0.0f;              // never beats bV under (>, oidx<)
            }
        }
        PACK2(rx2[p], __float_as_uint(c[0][0]), __float_as_uint(c[1][0]));
        PACK2(ry2[p], __float_as_uint(c[0][1]), __float_as_uint(c[1][1]));
        PACK2(rz2[p], __float_as_uint(c[0][2]), __float_as_uint(c[1][2]));
    }

    // ---- warp bounding box (coords >= 0 => f32 bits u32-monotone) ----
    const float wxlo = __uint_as_float(__reduce_min_sync(0xffffffffu, __float_as_uint(txlo)));
    const float wylo = __uint_as_float(__reduce_min_sync(0xffffffffu, __float_as_uint(tylo)));
    const float wzlo = __uint_as_float(__reduce_min_sync(0xffffffffu, __float_as_uint(tzlo)));
    const float wxhi = __uint_as_float(__reduce_max_sync(0xffffffffu, __float_as_uint(txhi)));
    const float wyhi = __uint_as_float(__reduce_max_sync(0xffffffffu, __float_as_uint(tyhi)));
    const float wzhi = __uint_as_float(__reduce_max_sync(0xffffffffu, __float_as_uint(tzhi)));

    // warp winner cache
    float    cwV   = finf();              // forces update on first iteration
    unsigned cwv   = 0, cwo = 0xffffffffu;
    int      cwpos = 0;
    bool     cwin  = (lane == 0);

    // fallback region init
    float* gmind = g_mind + b * NPTS;
    for (int i = REGN + tid; i < cnt; i += FPS_THREADS) gmind[i] = finf();
    __syncthreads();

    // ---- first pick = first masked point (compaction order) ----
    float4 p0 = cp[0];
    float lx = p0.x, ly = p0.y, lz = p0.z;
    if (tid == 0) g_fps[b * MM] = firstOidx;

    for (int it = 1; it < MM; ++it) {
        const unsigned ph = (unsigned)(it - 1) & 1u;

        // --- warp-uniform skip test ---
        float cdx = fmaxf(fmaxf(wxlo - lx, lx - wxhi), 0.0f);
        float cdy = fmaxf(fmaxf(wylo - ly, ly - wyhi), 0.0f);
        float cdz = fmaxf(fmaxf(wzlo - lz, lz - wzhi), 0.0f);
        float lb = cdx * cdx + cdy * cdy + cdz * cdz;
        const bool skip = (!havefb) && (lb * 0.99999f >= cwV);

        if (!skip) {
            unsigned long long nlx2, nly2, nlz2;
            {
                unsigned nx = __float_as_uint(-lx);
                unsigned ny = __float_as_uint(-ly);
                unsigned nz = __float_as_uint(-lz);
                PACK2(nlx2, nx, nx);
                PACK2(nly2, ny, ny);
                PACK2(nlz2, nz, nz);
            }
            float    bV = 0.0f;
            unsigned bO = 0xffffffffu;
            int      bP = 0;
            #pragma unroll
            for (int p = 0; p < PAIRS; ++p) {
                unsigned long long dx2, dy2, dz2, s2;
                ADD2(dx2, rx2[p], nlx2);
                MUL2(dx2, dx2, dx2);
                ADD2(dy2, ry2[p], nly2);
                MUL2(dy2, dy2, dy2);
                ADD2(s2, dx2, dy2);
                ADD2(dz2, rz2[p], nlz2);
                MUL2(dz2, dz2, dz2);
                ADD2(s2, s2, dz2);           // ((dx2+dy2)+dz2) — XLA order
                unsigned dlo, dhi;
                UNPACK2(dlo, dhi, s2);
                const int k0 = 2 * p, k1 = 2 * p + 1;
                float m0 = fminf(md[k0], __uint_as_float(dlo));
                float m1 = fminf(md[k1], __uint_as_float(dhi));
                md[k0] = m0;
                md[k1] = m1;
                if (m0 > bV || (m0 == bV && ox[k0] < bO)) { bV = m0; bO = ox[k0]; bP = base + k0; }
                if (m1 > bV || (m1 == bV && ox[k1] < bO)) { bV = m1; bO = ox[k1]; bP = base + k1; }
            }
            // fallback region (cnt > 5120; pruning disabled in this mode)
            if (havefb) {
                for (int i = REGN + tid; i < cnt; i += FPS_THREADS) {
                    float4 q = scp[i];
                    float dx = q.x - lx;
                    float dy = q.y - ly;
                    float dz = q.z - lz;
                    float d = __fadd_rn(__fadd_rn(__fmul_rn(dx, dx),
                                                  __fmul_rn(dy, dy)),
                                        __fmul_rn(dz, dz));
                    float m = fminf(gmind[i], d);
                    gmind[i] = m;
                    unsigned o = __float_as_uint(q.w);
                    if (m > bV || (m == bV && o < bO)) { bV = m; bO = o; bP = i; }
                }
            }
            // warp argmax: max value, then min oidx among ties
            unsigned vb = __float_as_uint(bV);
            unsigned wv = __reduce_max_sync(0xffffffffu, vb);
            unsigned wo = __reduce_min_sync(0xffffffffu, (vb == wv) ? bO : 0xffffffffu);
            // refresh cache (REDUX broadcasts to all lanes)
            cwv = wv;
            cwo = wo;
            cwV = __uint_as_float(wv);
            cwin = (vb == wv && bO == wo);   // unique winner lane (oidx unique)
            cwpos = bP;
        }

        if (cwin)
            { s_val[ph][wid] = ((unsigned long long)cwv << 32) | (unsigned)(~cwo);
              s_pos[ph][wid] = cwpos; }
        __syncthreads();

        // --- cross-warp argmax over 16 entries, redundant in every warp ---
        unsigned long long e = s_val[ph][lane & (FPS_WARPS - 1)];
        unsigned hv = (unsigned)(e >> 32);
        unsigned lv = (unsigned)e;             // ~oidx
        unsigned gv = __reduce_max_sync(0xffffffffu, hv);
        unsigned gl = __reduce_max_sync(0xffffffffu, (hv == gv) ? lv : 0u);
        unsigned wb2 = __ballot_sync(0xffffffffu, (hv == gv) & (lv == gl));
        int entry = __ffs(wb2) - 1;            // lanes 0..15 hold entries 0..15
        unsigned gOidx = ~gl;

        if (gv == 0u) {                        // degenerate: all minds zero
            gOidx = (unsigned)firstOidx;
            lx = pcb[3 * gOidx];
            ly = pcb[3 * gOidx + 1];
            lz = pcb[3 * gOidx + 2];
        } else {
            int pos = s_pos[ph][entry];
            float4 w = scp[pos];
            lx = w.x; ly = w.y; lz = w.z;
        }

        if (tid == 0) g_fps[b * MM + it] = (int)gOidx;
    }
}

// ============================================================================
// Kernel 2: three_nn — warp serves 4 queries; lane loads each tile point once.
// ============================================================================
#define NNQ 4
#define NNT 256
#define NNW (NNT / 32)
#define QPB (NNW * NNQ)    // 32 queries per block
#define NTS 2048

__global__ __launch_bounds__(NNT, 1)
void nn_kernel()
{
    __shared__ float4 s_pts[NTS];

    const int tid  = threadIdx.x;
    const int lane = tid & 31;
    const int wid  = tid >> 5;
    const int b    = blockIdx.x / (MM / QPB);
    const int q0   = blockIdx.x * QPB + wid * NNQ;

    const float4* pc4b = g_pc4 + (size_t)b * NPTS;

    float qx[NNQ], qy[NNQ], qz[NNQ];
    #pragma unroll
    for (int t = 0; t < NNQ; ++t) {
        const float4 qp = pc4b[g_fps[q0 + t]];
        qx[t] = qp.x; qy[t] = qp.y; qz[t] = qp.z;
    }

    float d0[NNQ], d1[NNQ], d2[NNQ];
    int   i0[NNQ], i1[NNQ], i2[NNQ];
    #pragma unroll
    for (int t = 0; t < NNQ; ++t) {
        d0[t] = finf(); d1[t] = finf(); d2[t] = finf();
        i0[t] = -1;     i1[t] = -1;     i2[t] = -1;
    }

    for (int t0 = 0; t0 < NPTS; t0 += NTS) {
        const int ts = min(NTS, NPTS - t0);
        __syncthreads();
        for (int j = tid; j < ts; j += NNT)
            s_pts[j] = pc4b[t0 + j];
        __syncthreads();

        for (int j = lane; j < ts; j += 32) {
            const float4 w = s_pts[j];
            const int gi = t0 + j;
            #pragma unroll
            for (int t = 0; t < NNQ; ++t) {
                float dx = w.x - qx[t];
                float dy = w.y - qy[t];
                float dz = w.z - qz[t];
                float d = fmaf(dz, dz, fmaf(dy, dy, dx * dx));
                if (d < d2[t]) {
                    if (d < d1[t]) {
                        if (d < d0[t]) { d2[t] = d1[t]; i2[t] = i1[t];
                                         d1[t] = d0[t]; i1[t] = i0[t];
                                         d0[t] = d;     i0[t] = gi; }
                        else           { d2[t] = d1[t]; i2[t] = i1[t];
                                         d1[t] = d;     i1[t] = gi; }
                    } else             { d2[t] = d;     i2[t] = gi; }
                }
            }
        }
    }

    #pragma unroll
    for (int t = 0; t < NNQ; ++t) {
        #pragma unroll
        for (int off = 16; off; off >>= 1) {
            float od0 = __shfl_down_sync(0xffffffffu, d0[t], off);
            float od1 = __shfl_down_sync(0xffffffffu, d1[t], off);
            float od2 = __shfl_down_sync(0xffffffffu, d2[t], off);
            int   oi0 = __shfl_down_sync(0xffffffffu, i0[t], off);
            int   oi1 = __shfl_down_sync(0xffffffffu, i1[t], off);
            int   oi2 = __shfl_down_sync(0xffffffffu, i2[t], off);
            #pragma unroll
            for (int k = 0; k < 3; ++k) {
                float d = (k == 0) ? od0 : (k == 1) ? od1 : od2;
                int   i = (k == 0) ? oi0 : (k == 1) ? oi1 : oi2;
                bool l2 = (d < d2[t]) || (d == d2[t] && i < i2[t]);
                if (l2) {
                    bool l1 = (d < d1[t]) || (d == d1[t] && i < i1[t]);
                    if (l1) {
                        bool l0 = (d < d0[t]) || (d == d0[t] && i < i0[t]);
                        if (l0) { d2[t] = d1[t]; i2[t] = i1[t];
                                  d1[t] = d0[t]; i1[t] = i0[t];
                                  d0[t] = d;     i0[t] = i; }
                        else    { d2[t] = d1[t]; i2[t] = i1[t];
                                  d1[t] = d;     i1[t] = i; }
                    } else      { d2[t] = d;     i2[t] = i; }
                }
            }
        }
        if (lane == 0) {
            const int q = q0 + t;
            float e0 = sqrtf(fmaxf(d0[t], 0.0f));
            float e1 = sqrtf(fmaxf(d1[t], 0.0f));
            float e2 = sqrtf(fmaxf(d2[t], 0.0f));
            float w0 = 1.0f / (e0 + 1e-8f);
            float w1 = 1.0f / (e1 + 1e-8f);
            float w2 = 1.0f / (e2 + 1e-8f);
            float s  = __fadd_rn(__fadd_rn(w0, w1), w2);
            g_w[3 * q + 0] = w0 / s;
            g_w[3 * q + 1] = w1 / s;
            g_w[3 * q + 2] = w2 / s;
            g_nn[3 * q + 0] = i0[t];
            g_nn[3 * q + 1] = i1[t];
            g_nn[3 * q + 2] = i2[t];
        }
    }
}

// ============================================================================
// Kernel 3: IDW feature interpolation.
// ============================================================================
__global__ __launch_bounds__(256)
void interp_kernel(const float* __restrict__ feat, float* __restrict__ out)
{
    int e = blockIdx.x * blockDim.x + threadIdx.x;
    if (e >= BB * CC * MM) return;
    const int m = e % MM;
    const int c = (e / MM) % CC;
    const int b = e / (MM * CC);
    const int q = b * MM + m;

    const int   j0 = g_nn[3 * q],     j1 = g_nn[3 * q + 1], j2 = g_nn[3 * q + 2];
    const float w0 = g_w[3 * q],      w1 = g_w[3 * q + 1],  w2 = g_w[3 * q + 2];
    const float* f = feat + ((size_t)b * CC + c) * NPTS;
    out[e] = w0 * f[j0] + w1 * f[j1] + w2 * f[j2];
}

// ============================================================================
extern "C" void kernel_launch(void* const* d_in, const int* in_sizes, int n_in,
                              void* d_out, int out_size)
{
    const float* pc   = (const float*)d_in[0];  // (B,N,3)
    const float* feat = (const float*)d_in[1];  // (B,C,N)
    const float* obj  = (const float*)d_in[2];  // (B,2,N)
    const float* gr   = (const float*)d_in[3];  // (B,N)
    float* out = (float*)d_out;                 // (B,C,M)

    pack_kernel<<<(BB * NPTS + 255) / 256, 256>>>(pc);
    fps_kernel<<<BB, FPS_THREADS>>>(pc, obj, gr);
    nn_kernel<<<(BB * MM) / QPB, NNT>>>();
    interp_kernel<<<(BB * CC * MM + 255) / 256, 256>>>(feat, out);
}